// round 3
// baseline (speedup 1.0000x reference)
#include <cuda_runtime.h>

#define Bn 128
#define Sn 500
#define Dn 32
#define Hn 8
#define HSn 4
#define BHn (Bn*Hn)        // 1024
#define FCIN (Sn*Dn)       // 16000
#define N1 1024
#define KSPLIT 25
#define KSPAN (FCIN/KSPLIT) // 640
#define BKt 16
#define NT (KSPAN/BKt)      // 40
#define NBt 16              // n-blocks of 64

typedef unsigned long long u64;

// ---------------- scratch (no allocation allowed) ----------------
__device__ float g_q[BHn*Sn*HSn];
__device__ float g_k[BHn*Sn*HSn];
__device__ float g_v[BHn*Sn*HSn];
__device__ float g_av[Bn*Sn*Dn];
__device__ float g_flatT[FCIN*Bn];          // [16000][128]
__device__ float g_part[KSPLIT*Bn*N1];      // split-K partials [ks][m][n]

// ---------------- f32x2 helpers ----------------
__device__ __forceinline__ u64 pack2(float lo, float hi){ u64 r; asm("mov.b64 %0,{%1,%2};" : "=l"(r) : "f"(lo),"f"(hi)); return r; }
__device__ __forceinline__ void unpack2(u64 v, float& lo, float& hi){ asm("mov.b64 {%0,%1},%2;" : "=f"(lo),"=f"(hi) : "l"(v)); }
__device__ __forceinline__ u64 fma2(u64 a,u64 b,u64 c){ u64 d; asm("fma.rn.f32x2 %0,%1,%2,%3;" : "=l"(d) : "l"(a),"l"(b),"l"(c)); return d; }
__device__ __forceinline__ u64 mul2(u64 a,u64 b){ u64 d; asm("mul.rn.f32x2 %0,%1,%2;" : "=l"(d) : "l"(a),"l"(b)); return d; }
__device__ __forceinline__ u64 add2(u64 a,u64 b){ u64 d; asm("add.rn.f32x2 %0,%1,%2;" : "=l"(d) : "l"(a),"l"(b)); return d; }
// packed ex2: results born in the halves of the output pair (ptxas can elide movs)
__device__ __forceinline__ u64 ex2_2(u64 x){
    u64 r;
    asm("{\n\t.reg .f32 a,b;\n\t"
        "mov.b64 {a,b},%1;\n\t"
        "ex2.approx.ftz.f32 a,a;\n\t"
        "ex2.approx.ftz.f32 b,b;\n\t"
        "mov.b64 %0,{a,b};\n\t}" : "=l"(r) : "l"(x));
    return r;
}
__device__ __forceinline__ unsigned smem_u32(const void* p){ return (unsigned)__cvta_generic_to_shared(p); }
__device__ __forceinline__ void cpasync16(unsigned dst, const void* src){
    asm volatile("cp.async.ca.shared.global [%0], [%1], 16;" :: "r"(dst), "l"(src) : "memory");
}
__device__ __forceinline__ void cpcommit(){ asm volatile("cp.async.commit_group;" ::: "memory"); }
__device__ __forceinline__ void cpwait0(){ asm volatile("cp.async.wait_group 0;" ::: "memory"); }

#define QSCALE 0.72134752044448169f   // (1/sqrt(4)) * log2(e), folded into q

// ================= K1: QKV projection =================
__global__ __launch_bounds__(256) void k_qkv(const float* __restrict__ x,
    const float* __restrict__ Wq, const float* __restrict__ bq,
    const float* __restrict__ Wk, const float* __restrict__ bk,
    const float* __restrict__ Wv, const float* __restrict__ bv)
{
    __shared__ float ws[3*1024];
    __shared__ float bs[3*32];
    __shared__ float xs[8*32];
    int tid = threadIdx.x;
    for(int i=tid;i<1024;i+=256){ ws[i]=Wq[i]; ws[1024+i]=Wk[i]; ws[2048+i]=Wv[i]; }
    if(tid<32){ bs[tid]=bq[tid]; bs[32+tid]=bk[tid]; bs[64+tid]=bv[tid]; }
    int row0 = blockIdx.x*8;
    xs[tid]=x[row0*32+tid];
    __syncthreads();
    #pragma unroll
    for(int t=0;t<3;t++){
        int o = tid + t*256;
        int row = o/96; int cc = o - row*96;
        int which = cc>>5; int ch = cc&31;
        const float* w  = ws + which*1024 + ch*32;
        const float* xr = xs + row*32;
        float sum = bs[which*32+ch];
        #pragma unroll
        for(int i=0;i<32;i++) sum += xr[i]*w[i];
        int gr = row0+row; int b = gr/Sn; int s = gr - b*Sn;
        int idx = ((b*Hn + (ch>>2))*Sn + s)*HSn + (ch&3);
        if(which==0)      g_q[idx] = sum*QSCALE;
        else if(which==1) g_k[idx] = sum;
        else              g_v[idx] = sum;
    }
}

// ================= K2: attention per (b,h) =================
__global__ __launch_bounds__(128) void k_attn()
{
    __shared__ __align__(16) u64 kk[Sn*HSn];
    __shared__ __align__(16) u64 vv[Sn*HSn];
    int tid=threadIdx.x; int bh=blockIdx.x;
    int base = bh*Sn*HSn;
    for(int i=tid;i<Sn*HSn;i+=128){
        float f=g_k[base+i]; kk[i]=pack2(f,f);
        float g=g_v[base+i]; vv[i]=pack2(g,g);
    }
    __syncthreads();
    if(tid<125){
        int r0=tid, r1=tid+125, r2=tid+250, r3=tid+375;
        const float4* q4=(const float4*)(g_q+base);
        float4 qa=q4[r0], qb=q4[r1], qc=q4[r2], qd=q4[r3];
        u64 qp01[4]={pack2(qa.x,qb.x),pack2(qa.y,qb.y),pack2(qa.z,qb.z),pack2(qa.w,qb.w)};
        u64 qp23[4]={pack2(qc.x,qd.x),pack2(qc.y,qd.y),pack2(qc.z,qd.z),pack2(qc.w,qd.w)};
        u64 acc01[4]={0,0,0,0}, acc23[4]={0,0,0,0};
        u64 l01=0, l23=0;
        #pragma unroll 2
        for(int j=0;j<Sn;j++){
            const ulonglong2* kj=(const ulonglong2*)(kk + j*HSn);
            ulonglong2 K0=kj[0], K1=kj[1];
            u64 d01 = mul2(qp01[0],K0.x); d01=fma2(qp01[1],K0.y,d01);
            d01=fma2(qp01[2],K1.x,d01);   d01=fma2(qp01[3],K1.y,d01);
            u64 d23 = mul2(qp23[0],K0.x); d23=fma2(qp23[1],K0.y,d23);
            d23=fma2(qp23[2],K1.x,d23);   d23=fma2(qp23[3],K1.y,d23);
            u64 p01 = ex2_2(d01);
            u64 p23 = ex2_2(d23);
            l01=add2(l01,p01); l23=add2(l23,p23);
            const ulonglong2* vj=(const ulonglong2*)(vv + j*HSn);
            ulonglong2 V0=vj[0], V1=vj[1];
            acc01[0]=fma2(p01,V0.x,acc01[0]); acc01[1]=fma2(p01,V0.y,acc01[1]);
            acc01[2]=fma2(p01,V1.x,acc01[2]); acc01[3]=fma2(p01,V1.y,acc01[3]);
            acc23[0]=fma2(p23,V0.x,acc23[0]); acc23[1]=fma2(p23,V0.y,acc23[1]);
            acc23[2]=fma2(p23,V1.x,acc23[2]); acc23[3]=fma2(p23,V1.y,acc23[3]);
        }
        int b=bh>>3, h=bh&7;
        float l0,l1,l2,l3; unpack2(l01,l0,l1); unpack2(l23,l2,l3);
        float i0=1.f/l0, i1=1.f/l1, i2=1.f/l2, i3=1.f/l3;
        float lo,hi; float4 o0,o1,o2,o3;
        unpack2(acc01[0],lo,hi); o0.x=lo*i0; o1.x=hi*i1;
        unpack2(acc01[1],lo,hi); o0.y=lo*i0; o1.y=hi*i1;
        unpack2(acc01[2],lo,hi); o0.z=lo*i0; o1.z=hi*i1;
        unpack2(acc01[3],lo,hi); o0.w=lo*i0; o1.w=hi*i1;
        unpack2(acc23[0],lo,hi); o2.x=lo*i2; o3.x=hi*i3;
        unpack2(acc23[1],lo,hi); o2.y=lo*i2; o3.y=hi*i3;
        unpack2(acc23[2],lo,hi); o2.z=lo*i2; o3.z=hi*i3;
        unpack2(acc23[3],lo,hi); o2.w=lo*i2; o3.w=hi*i3;
        float* outb = g_av + b*(Sn*Dn) + h*HSn;
        *(float4*)(outb + r0*Dn) = o0;
        *(float4*)(outb + r1*Dn) = o1;
        *(float4*)(outb + r2*Dn) = o2;
        *(float4*)(outb + r3*Dn) = o3;
    }
}

// ================= K3: Wo projection, writes TRANSPOSED flat =================
__global__ __launch_bounds__(256) void k_proj(const float* __restrict__ Wo,
                                              const float* __restrict__ bo)
{
    __shared__ float avs[128*33];
    __shared__ float wos[1024];
    __shared__ float bos[32];
    int tid=threadIdx.x; int s=blockIdx.x;
    for(int i=tid;i<1024;i+=256) wos[i]=Wo[i];
    if(tid<32) bos[tid]=bo[tid];
    for(int i=tid;i<4096;i+=256){ int bb=i>>5, c=i&31; avs[bb*33+c]=g_av[bb*(Sn*Dn)+s*Dn+c]; }
    __syncthreads();
    #pragma unroll
    for(int t=0;t<16;t++){
        int o=tid+t*256; int bb=o&127, c=o>>7;
        const float* av=avs+bb*33; const float* w=wos+c*32;
        float sum=bos[c];
        #pragma unroll
        for(int i=0;i<32;i++) sum+=av[i]*w[i];
        g_flatT[(s*32+c)*Bn + bb] = sum;
    }
}

// ================= K4: FC1 split-K GEMM v3 =================
// grid (16 n-blocks, 25 k-splits) = 400 CTAs, 64 thr.
// CTA tile: 128m x 64n. Thread tile: 8 m-pairs x 8 n = 64 FFMA2/kk, 8 LDS.128/kk.
// bytes/MAC = 1.0 -> crossbar floor == FMA floor (~62us).
// B smem layout interleaved: u64 index (q*8+tn)*2+e  (q=j>>1, e=j&1) -> both A and B
// inner-loop LDS.128 conflict-free. Output staged through smem -> coalesced STG.128.
__global__ __launch_bounds__(64) void k_fc1(const float* __restrict__ W1)
{
    __shared__ __align__(16) u64 As[2][BKt*64];   // 8KB each: [kk][pair]
    __shared__ __align__(16) u64 Bs[2][BKt*64];   // 8KB each: [kk][interleaved dup]
    int tid=threadIdx.x;
    int n0=blockIdx.x*64, k0=blockIdx.y*KSPAN;
    int tp=tid>>3, tn=tid&7;
    u64 acc[64];
    #pragma unroll
    for(int i=0;i<64;i++) acc[i]=0;

    const char* aSrcBase=(const char*)g_flatT + (size_t)k0*512;  // 128 floats/row
    unsigned aDst0 = smem_u32(As[0]) + (unsigned)tid*16;
    unsigned aDst1 = smem_u32(As[1]) + (unsigned)tid*16;
    // B: thread owns W1 row n0+tid; dup-store slot index:
    const float* wRow = W1 + (size_t)(n0+tid)*FCIN + k0;
    int bIdx = ((tid&7)>>1)*16 + (tid>>3)*2 + (tid&1);

    // prologue: tile 0
    {
        #pragma unroll
        for(int j=0;j<8;j++) cpasync16(aDst0 + j*1024, aSrcBase + tid*16 + j*1024);
        cpcommit();
        float4 f0=*(const float4*)(wRow), f1=*(const float4*)(wRow+4);
        float4 f2=*(const float4*)(wRow+8), f3=*(const float4*)(wRow+12);
        u64* B=Bs[0];
        B[ 0*64+bIdx]=pack2(f0.x,f0.x); B[ 1*64+bIdx]=pack2(f0.y,f0.y);
        B[ 2*64+bIdx]=pack2(f0.z,f0.z); B[ 3*64+bIdx]=pack2(f0.w,f0.w);
        B[ 4*64+bIdx]=pack2(f1.x,f1.x); B[ 5*64+bIdx]=pack2(f1.y,f1.y);
        B[ 6*64+bIdx]=pack2(f1.z,f1.z); B[ 7*64+bIdx]=pack2(f1.w,f1.w);
        B[ 8*64+bIdx]=pack2(f2.x,f2.x); B[ 9*64+bIdx]=pack2(f2.y,f2.y);
        B[10*64+bIdx]=pack2(f2.z,f2.z); B[11*64+bIdx]=pack2(f2.w,f2.w);
        B[12*64+bIdx]=pack2(f3.x,f3.x); B[13*64+bIdx]=pack2(f3.y,f3.y);
        B[14*64+bIdx]=pack2(f3.z,f3.z); B[15*64+bIdx]=pack2(f3.w,f3.w);
    }

    for(int t=0;t<NT;t++){
        cpwait0();
        __syncthreads();
        if(t+1<NT){
            int nb=(t+1)&1;
            const char* a = aSrcBase + (size_t)(t+1)*8192;
            unsigned d = nb? aDst1 : aDst0;
            #pragma unroll
            for(int j=0;j<8;j++) cpasync16(d + j*1024, a + tid*16 + j*1024);
            cpcommit();
            const float* w = wRow + (t+1)*BKt;
            float4 f0=*(const float4*)(w), f1=*(const float4*)(w+4);
            float4 f2=*(const float4*)(w+8), f3=*(const float4*)(w+12);
            u64* B=Bs[nb];
            B[ 0*64+bIdx]=pack2(f0.x,f0.x); B[ 1*64+bIdx]=pack2(f0.y,f0.y);
            B[ 2*64+bIdx]=pack2(f0.z,f0.z); B[ 3*64+bIdx]=pack2(f0.w,f0.w);
            B[ 4*64+bIdx]=pack2(f1.x,f1.x); B[ 5*64+bIdx]=pack2(f1.y,f1.y);
            B[ 6*64+bIdx]=pack2(f1.z,f1.z); B[ 7*64+bIdx]=pack2(f1.w,f1.w);
            B[ 8*64+bIdx]=pack2(f2.x,f2.x); B[ 9*64+bIdx]=pack2(f2.y,f2.y);
            B[10*64+bIdx]=pack2(f2.z,f2.z); B[11*64+bIdx]=pack2(f2.w,f2.w);
            B[12*64+bIdx]=pack2(f3.x,f3.x); B[13*64+bIdx]=pack2(f3.y,f3.y);
            B[14*64+bIdx]=pack2(f3.z,f3.z); B[15*64+bIdx]=pack2(f3.w,f3.w);
        }
        const u64* A=As[t&1]; const u64* B=Bs[t&1];
        #pragma unroll
        for(int kkk=0;kkk<BKt;kkk++){
            const ulonglong2* ap=(const ulonglong2*)(A + kkk*64 + tp*2);
            ulonglong2 A0=ap[0],A1=ap[8],A2=ap[16],A3=ap[24];
            const ulonglong2* bp=(const ulonglong2*)(B + kkk*64 + tn*2);
            ulonglong2 B0=bp[0],B1=bp[8],B2=bp[16],B3=bp[24];
            u64 a_[8]={A0.x,A0.y,A1.x,A1.y,A2.x,A2.y,A3.x,A3.y};
            u64 b_[8]={B0.x,B0.y,B1.x,B1.y,B2.x,B2.y,B3.x,B3.y};
            #pragma unroll
            for(int i=0;i<8;i++)
                #pragma unroll
                for(int j=0;j<8;j++)
                    acc[i*8+j]=fma2(a_[i],b_[j],acc[i*8+j]);
        }
    }

    // ---- staged, coalesced partial writes: g_part[ks][m][n] ----
    float* smf = (float*)As;     // 16KB = 64m x 64n floats
    int ks = blockIdx.y;
    #pragma unroll
    for(int c=0;c<2;c++){
        __syncthreads();
        #pragma unroll
        for(int qq=0;qq<2;qq++){
            #pragma unroll
            for(int e=0;e<2;e++){
                int ii = c*4 + qq*2 + e;
                int mi = 4*tp + 32*qq + 2*e;
                #pragma unroll
                for(int jj=0;jj<8;jj++){
                    float lo,hi; unpack2(acc[ii*8+jj],lo,hi);
                    int nl = tn*8+jj;
                    smf[mi*64+nl]=lo;
                    smf[(mi+1)*64+nl]=hi;
                }
            }
        }
        __syncthreads();
        #pragma unroll
        for(int i=0;i<16;i++){
            int fid = i*64 + tid;           // float4 id 0..1023
            int row = fid>>4, col4 = fid&15;
            float4 v = *(const float4*)(smf + row*64 + col4*4);
            *(float4*)(g_part + ((size_t)(ks*Bn) + c*64 + row)*N1 + n0 + col4*4) = v;
        }
    }
}

// ================= K5: split-K reduce + FC2 + FC3 =================
__global__ __launch_bounds__(256) void k_fc23(const float* __restrict__ b1,
    const float* __restrict__ W2, const float* __restrict__ b2,
    const float* __restrict__ W3, const float* __restrict__ b3,
    float* __restrict__ dout)
{
    __shared__ float y1[1024];
    __shared__ float w2s[64*64];
    __shared__ float partial[4*64];
    __shared__ float out1s[64];
    int tid=threadIdx.x; int b=blockIdx.x;
    for(int n=tid;n<1024;n+=256){
        float sum=b1[n];
        #pragma unroll
        for(int ks=0;ks<KSPLIT;ks++) sum+=g_part[((size_t)ks*Bn+b)*N1+n];
        y1[n]=sum;
    }
    int o=tid&63, part=tid>>6;
    float acc=0.f;
    for(int chunk=0;chunk<16;chunk++){
        int kbase=chunk*64;
        __syncthreads();
        #pragma unroll
        for(int i=0;i<4;i++){
            int lin=tid+i*256; int row=lin>>4, col4=lin&15;
            float4 f=*(const float4*)(W2 + row*1024 + kbase + col4*4);
            w2s[(col4*4+0)*64+row]=f.x;
            w2s[(col4*4+1)*64+row]=f.y;
            w2s[(col4*4+2)*64+row]=f.z;
            w2s[(col4*4+3)*64+row]=f.w;
        }
        __syncthreads();
        #pragma unroll
        for(int i=0;i<16;i++){
            int k=part*16+i;
            acc += y1[kbase+k]*w2s[k*64+o];
        }
    }
    partial[part*64+o]=acc;
    __syncthreads();
    if(tid<64){
        float v=partial[tid]+partial[64+tid]+partial[128+tid]+partial[192+tid]+b2[tid];
        out1s[tid]=v;
        dout[b*64+tid]=v;
    }
    __syncthreads();
    if(tid<2){
        float s=b3[tid];
        #pragma unroll
        for(int k=0;k<64;k++) s+=out1s[k]*W3[tid*64+k];
        dout[Bn*64 + b*2 + tid]=s;
    }
}

// ================= launch =================
extern "C" void kernel_launch(void* const* d_in, const int* in_sizes, int n_in,
                              void* d_out, int out_size)
{
    const float* x =(const float*)d_in[0];
    const float* Wq=(const float*)d_in[1];  const float* bq=(const float*)d_in[2];
    const float* Wk=(const float*)d_in[3];  const float* bk=(const float*)d_in[4];
    const float* Wv=(const float*)d_in[5];  const float* bv=(const float*)d_in[6];
    const float* Wo=(const float*)d_in[7];  const float* bo=(const float*)d_in[8];
    const float* W1=(const float*)d_in[9];  const float* b1=(const float*)d_in[10];
    const float* W2=(const float*)d_in[11]; const float* b2=(const float*)d_in[12];
    const float* W3=(const float*)d_in[13]; const float* b3=(const float*)d_in[14];
    float* out=(float*)d_out;

    k_qkv <<<(Bn*Sn)/8, 256>>>(x,Wq,bq,Wk,bk,Wv,bv);
    k_attn<<<BHn, 128>>>();
    k_proj<<<Sn, 256>>>(Wo,bo);
    k_fc1 <<<dim3(NBt,KSPLIT), 64>>>(W1);
    k_fc23<<<Bn, 256>>>(b1,W2,b2,W3,b3,out);
}

// round 4
// speedup vs baseline: 1.4927x; 1.4927x over previous
#include <cuda_runtime.h>

#define Bn 128
#define Sn 500
#define Dn 32
#define Hn 8
#define HSn 4
#define BHn (Bn*Hn)        // 1024
#define FCIN (Sn*Dn)       // 16000
#define N1 1024
#define KSPLIT 50
#define KSPAN (FCIN/KSPLIT) // 320
#define BKt 16
#define NT (KSPAN/BKt)      // 20
#define NBt 16              // n-blocks of 64

typedef unsigned long long u64;

// ---------------- scratch (no allocation allowed) ----------------
__device__ float g_q[BHn*Sn*HSn];
__device__ float g_k[BHn*Sn*HSn];
__device__ float g_v[BHn*Sn*HSn];
__device__ float g_av[Bn*Sn*Dn];
__device__ float g_flatT[FCIN*Bn];          // [16000][128]
__device__ float g_part[KSPLIT*Bn*N1];      // split-K partials [ks][m][n]

// ---------------- f32x2 helpers ----------------
__device__ __forceinline__ u64 pack2(float lo, float hi){ u64 r; asm("mov.b64 %0,{%1,%2};" : "=l"(r) : "f"(lo),"f"(hi)); return r; }
__device__ __forceinline__ void unpack2(u64 v, float& lo, float& hi){ asm("mov.b64 {%0,%1},%2;" : "=f"(lo),"=f"(hi) : "l"(v)); }
__device__ __forceinline__ u64 fma2(u64 a,u64 b,u64 c){ u64 d; asm("fma.rn.f32x2 %0,%1,%2,%3;" : "=l"(d) : "l"(a),"l"(b),"l"(c)); return d; }
__device__ __forceinline__ u64 mul2(u64 a,u64 b){ u64 d; asm("mul.rn.f32x2 %0,%1,%2;" : "=l"(d) : "l"(a),"l"(b)); return d; }
__device__ __forceinline__ u64 add2(u64 a,u64 b){ u64 d; asm("add.rn.f32x2 %0,%1,%2;" : "=l"(d) : "l"(a),"l"(b)); return d; }
__device__ __forceinline__ u64 ex2_2(u64 x){
    u64 r;
    asm("{\n\t.reg .f32 a,b;\n\t"
        "mov.b64 {a,b},%1;\n\t"
        "ex2.approx.ftz.f32 a,a;\n\t"
        "ex2.approx.ftz.f32 b,b;\n\t"
        "mov.b64 %0,{a,b};\n\t}" : "=l"(r) : "l"(x));
    return r;
}
__device__ __forceinline__ unsigned smem_u32(const void* p){ return (unsigned)__cvta_generic_to_shared(p); }
__device__ __forceinline__ void cpasync16(unsigned dst, const void* src){
    asm volatile("cp.async.ca.shared.global [%0], [%1], 16;" :: "r"(dst), "l"(src) : "memory");
}
__device__ __forceinline__ void cpcommit(){ asm volatile("cp.async.commit_group;" ::: "memory"); }
__device__ __forceinline__ void cpwait0(){ asm volatile("cp.async.wait_group 0;" ::: "memory"); }

#define QSCALE 0.72134752044448169f   // (1/sqrt(4)) * log2(e), folded into q

// ================= K1: QKV projection =================
// Weight smem padded to stride 33 -> conflict-free lane access (bank=(ch+i)%32).
__global__ __launch_bounds__(256) void k_qkv(const float* __restrict__ x,
    const float* __restrict__ Wq, const float* __restrict__ bq,
    const float* __restrict__ Wk, const float* __restrict__ bk,
    const float* __restrict__ Wv, const float* __restrict__ bv)
{
    __shared__ float ws[3*1056];     // [which][ch][33]
    __shared__ float bs[3*32];
    __shared__ float xs[8*32];
    int tid = threadIdx.x;
    for(int i=tid;i<1024;i+=256){
        int ch=i>>5, k=i&31; int d=ch*33+k;
        ws[d]=Wq[i]; ws[1056+d]=Wk[i]; ws[2112+d]=Wv[i];
    }
    if(tid<32){ bs[tid]=bq[tid]; bs[32+tid]=bk[tid]; bs[64+tid]=bv[tid]; }
    int row0 = blockIdx.x*8;
    xs[tid]=x[row0*32+tid];
    __syncthreads();
    #pragma unroll
    for(int t=0;t<3;t++){
        int o = tid + t*256;
        int row = o/96; int cc = o - row*96;
        int which = cc>>5; int ch = cc&31;
        const float* w  = ws + which*1056 + ch*33;
        const float* xr = xs + row*32;
        float sum = bs[which*32+ch];
        #pragma unroll
        for(int i=0;i<32;i++) sum += xr[i]*w[i];
        int gr = row0+row; int b = gr/Sn; int s = gr - b*Sn;
        int idx = ((b*Hn + (ch>>2))*Sn + s)*HSn + (ch&3);
        if(which==0)      g_q[idx] = sum*QSCALE;
        else if(which==1) g_k[idx] = sum;
        else              g_v[idx] = sum;
    }
}

// ================= K2: attention per (b,h) =================
__global__ __launch_bounds__(128) void k_attn()
{
    __shared__ __align__(16) u64 kk[Sn*HSn];
    __shared__ __align__(16) u64 vv[Sn*HSn];
    int tid=threadIdx.x; int bh=blockIdx.x;
    int base = bh*Sn*HSn;
    for(int i=tid;i<Sn*HSn;i+=128){
        float f=g_k[base+i]; kk[i]=pack2(f,f);
        float g=g_v[base+i]; vv[i]=pack2(g,g);
    }
    __syncthreads();
    if(tid<125){
        int r0=tid, r1=tid+125, r2=tid+250, r3=tid+375;
        const float4* q4=(const float4*)(g_q+base);
        float4 qa=q4[r0], qb=q4[r1], qc=q4[r2], qd=q4[r3];
        u64 qp01[4]={pack2(qa.x,qb.x),pack2(qa.y,qb.y),pack2(qa.z,qb.z),pack2(qa.w,qb.w)};
        u64 qp23[4]={pack2(qc.x,qd.x),pack2(qc.y,qd.y),pack2(qc.z,qd.z),pack2(qc.w,qd.w)};
        u64 acc01[4]={0,0,0,0}, acc23[4]={0,0,0,0};
        u64 l01=0, l23=0;
        #pragma unroll 4
        for(int j=0;j<Sn;j++){
            const ulonglong2* kj=(const ulonglong2*)(kk + j*HSn);
            ulonglong2 K0=kj[0], K1=kj[1];
            u64 d01 = mul2(qp01[0],K0.x); d01=fma2(qp01[1],K0.y,d01);
            d01=fma2(qp01[2],K1.x,d01);   d01=fma2(qp01[3],K1.y,d01);
            u64 d23 = mul2(qp23[0],K0.x); d23=fma2(qp23[1],K0.y,d23);
            d23=fma2(qp23[2],K1.x,d23);   d23=fma2(qp23[3],K1.y,d23);
            u64 p01 = ex2_2(d01);
            u64 p23 = ex2_2(d23);
            l01=add2(l01,p01); l23=add2(l23,p23);
            const ulonglong2* vj=(const ulonglong2*)(vv + j*HSn);
            ulonglong2 V0=vj[0], V1=vj[1];
            acc01[0]=fma2(p01,V0.x,acc01[0]); acc01[1]=fma2(p01,V0.y,acc01[1]);
            acc01[2]=fma2(p01,V1.x,acc01[2]); acc01[3]=fma2(p01,V1.y,acc01[3]);
            acc23[0]=fma2(p23,V0.x,acc23[0]); acc23[1]=fma2(p23,V0.y,acc23[1]);
            acc23[2]=fma2(p23,V1.x,acc23[2]); acc23[3]=fma2(p23,V1.y,acc23[3]);
        }
        int b=bh>>3, h=bh&7;
        float l0,l1,l2,l3; unpack2(l01,l0,l1); unpack2(l23,l2,l3);
        float i0=1.f/l0, i1=1.f/l1, i2=1.f/l2, i3=1.f/l3;
        float lo,hi; float4 o0,o1,o2,o3;
        unpack2(acc01[0],lo,hi); o0.x=lo*i0; o1.x=hi*i1;
        unpack2(acc01[1],lo,hi); o0.y=lo*i0; o1.y=hi*i1;
        unpack2(acc01[2],lo,hi); o0.z=lo*i0; o1.z=hi*i1;
        unpack2(acc01[3],lo,hi); o0.w=lo*i0; o1.w=hi*i1;
        unpack2(acc23[0],lo,hi); o2.x=lo*i2; o3.x=hi*i3;
        unpack2(acc23[1],lo,hi); o2.y=lo*i2; o3.y=hi*i3;
        unpack2(acc23[2],lo,hi); o2.z=lo*i2; o3.z=hi*i3;
        unpack2(acc23[3],lo,hi); o2.w=lo*i2; o3.w=hi*i3;
        float* outb = g_av + b*(Sn*Dn) + h*HSn;
        *(float4*)(outb + r0*Dn) = o0;
        *(float4*)(outb + r1*Dn) = o1;
        *(float4*)(outb + r2*Dn) = o2;
        *(float4*)(outb + r3*Dn) = o3;
    }
}

// ================= K3: Wo projection, writes TRANSPOSED flat =================
__global__ __launch_bounds__(256) void k_proj(const float* __restrict__ Wo,
                                              const float* __restrict__ bo)
{
    __shared__ float avs[128*33];
    __shared__ float wos[1024];
    __shared__ float bos[32];
    int tid=threadIdx.x; int s=blockIdx.x;
    for(int i=tid;i<1024;i+=256) wos[i]=Wo[i];
    if(tid<32) bos[tid]=bo[tid];
    for(int i=tid;i<4096;i+=256){ int bb=i>>5, c=i&31; avs[bb*33+c]=g_av[bb*(Sn*Dn)+s*Dn+c]; }
    __syncthreads();
    #pragma unroll
    for(int t=0;t<16;t++){
        int o=tid+t*256; int bb=o&127, c=o>>7;
        const float* av=avs+bb*33; const float* w=wos+c*32;
        float sum=bos[c];
        #pragma unroll
        for(int i=0;i<32;i++) sum+=av[i]*w[i];
        g_flatT[(s*32+c)*Bn + bb] = sum;
    }
}

// ================= K4: FC1 split-K GEMM v3b =================
// grid (16 n-blocks, 50 k-splits) = 800 CTAs, 64 thr -> ~5 CTAs/SM (reg-capped).
__global__ __launch_bounds__(64,5) void k_fc1(const float* __restrict__ W1)
{
    __shared__ __align__(16) u64 As[2][BKt*64];
    __shared__ __align__(16) u64 Bs[2][BKt*64];
    int tid=threadIdx.x;
    int n0=blockIdx.x*64, k0=blockIdx.y*KSPAN;
    int tp=tid>>3, tn=tid&7;
    u64 acc[64];
    #pragma unroll
    for(int i=0;i<64;i++) acc[i]=0;

    const char* aSrcBase=(const char*)g_flatT + (size_t)k0*512;
    unsigned aDst0 = smem_u32(As[0]) + (unsigned)tid*16;
    unsigned aDst1 = smem_u32(As[1]) + (unsigned)tid*16;
    const float* wRow = W1 + (size_t)(n0+tid)*FCIN + k0;
    int bIdx = ((tid&7)>>1)*16 + (tid>>3)*2 + (tid&1);

    {
        #pragma unroll
        for(int j=0;j<8;j++) cpasync16(aDst0 + j*1024, aSrcBase + tid*16 + j*1024);
        cpcommit();
        float4 f0=*(const float4*)(wRow), f1=*(const float4*)(wRow+4);
        float4 f2=*(const float4*)(wRow+8), f3=*(const float4*)(wRow+12);
        u64* B=Bs[0];
        B[ 0*64+bIdx]=pack2(f0.x,f0.x); B[ 1*64+bIdx]=pack2(f0.y,f0.y);
        B[ 2*64+bIdx]=pack2(f0.z,f0.z); B[ 3*64+bIdx]=pack2(f0.w,f0.w);
        B[ 4*64+bIdx]=pack2(f1.x,f1.x); B[ 5*64+bIdx]=pack2(f1.y,f1.y);
        B[ 6*64+bIdx]=pack2(f1.z,f1.z); B[ 7*64+bIdx]=pack2(f1.w,f1.w);
        B[ 8*64+bIdx]=pack2(f2.x,f2.x); B[ 9*64+bIdx]=pack2(f2.y,f2.y);
        B[10*64+bIdx]=pack2(f2.z,f2.z); B[11*64+bIdx]=pack2(f2.w,f2.w);
        B[12*64+bIdx]=pack2(f3.x,f3.x); B[13*64+bIdx]=pack2(f3.y,f3.y);
        B[14*64+bIdx]=pack2(f3.z,f3.z); B[15*64+bIdx]=pack2(f3.w,f3.w);
    }

    for(int t=0;t<NT;t++){
        cpwait0();
        __syncthreads();
        if(t+1<NT){
            int nb=(t+1)&1;
            const char* a = aSrcBase + (size_t)(t+1)*8192;
            unsigned d = nb? aDst1 : aDst0;
            #pragma unroll
            for(int j=0;j<8;j++) cpasync16(d + j*1024, a + tid*16 + j*1024);
            cpcommit();
            const float* w = wRow + (t+1)*BKt;
            float4 f0=*(const float4*)(w), f1=*(const float4*)(w+4);
            float4 f2=*(const float4*)(w+8), f3=*(const float4*)(w+12);
            u64* B=Bs[nb];
            B[ 0*64+bIdx]=pack2(f0.x,f0.x); B[ 1*64+bIdx]=pack2(f0.y,f0.y);
            B[ 2*64+bIdx]=pack2(f0.z,f0.z); B[ 3*64+bIdx]=pack2(f0.w,f0.w);
            B[ 4*64+bIdx]=pack2(f1.x,f1.x); B[ 5*64+bIdx]=pack2(f1.y,f1.y);
            B[ 6*64+bIdx]=pack2(f1.z,f1.z); B[ 7*64+bIdx]=pack2(f1.w,f1.w);
            B[ 8*64+bIdx]=pack2(f2.x,f2.x); B[ 9*64+bIdx]=pack2(f2.y,f2.y);
            B[10*64+bIdx]=pack2(f2.z,f2.z); B[11*64+bIdx]=pack2(f2.w,f2.w);
            B[12*64+bIdx]=pack2(f3.x,f3.x); B[13*64+bIdx]=pack2(f3.y,f3.y);
            B[14*64+bIdx]=pack2(f3.z,f3.z); B[15*64+bIdx]=pack2(f3.w,f3.w);
        }
        const u64* A=As[t&1]; const u64* B=Bs[t&1];
        #pragma unroll
        for(int kkk=0;kkk<BKt;kkk++){
            const ulonglong2* ap=(const ulonglong2*)(A + kkk*64 + tp*2);
            ulonglong2 A0=ap[0],A1=ap[8],A2=ap[16],A3=ap[24];
            const ulonglong2* bp=(const ulonglong2*)(B + kkk*64 + tn*2);
            ulonglong2 B0=bp[0],B1=bp[8],B2=bp[16],B3=bp[24];
            u64 a_[8]={A0.x,A0.y,A1.x,A1.y,A2.x,A2.y,A3.x,A3.y};
            u64 b_[8]={B0.x,B0.y,B1.x,B1.y,B2.x,B2.y,B3.x,B3.y};
            #pragma unroll
            for(int i=0;i<8;i++)
                #pragma unroll
                for(int j=0;j<8;j++)
                    acc[i*8+j]=fma2(a_[i],b_[j],acc[i*8+j]);
        }
    }

    float* smf = (float*)As;
    int ks = blockIdx.y;
    #pragma unroll
    for(int c=0;c<2;c++){
        __syncthreads();
        #pragma unroll
        for(int qq=0;qq<2;qq++){
            #pragma unroll
            for(int e=0;e<2;e++){
                int ii = c*4 + qq*2 + e;
                int mi = 4*tp + 32*qq + 2*e;
                #pragma unroll
                for(int jj=0;jj<8;jj++){
                    float lo,hi; unpack2(acc[ii*8+jj],lo,hi);
                    int nl = tn*8+jj;
                    smf[mi*64+nl]=lo;
                    smf[(mi+1)*64+nl]=hi;
                }
            }
        }
        __syncthreads();
        #pragma unroll
        for(int i=0;i<16;i++){
            int fid = i*64 + tid;
            int row = fid>>4, col4 = fid&15;
            float4 v = *(const float4*)(smf + row*64 + col4*4);
            *(float4*)(g_part + ((size_t)(ks*Bn) + c*64 + row)*N1 + n0 + col4*4) = v;
        }
    }
}

// ================= K5: split-K reduce + FC2 + FC3 =================
__global__ __launch_bounds__(256) void k_fc23(const float* __restrict__ b1,
    const float* __restrict__ W2, const float* __restrict__ b2,
    const float* __restrict__ W3, const float* __restrict__ b3,
    float* __restrict__ dout)
{
    __shared__ float y1[1024];
    __shared__ float w2s[64*64];
    __shared__ float partial[4*64];
    __shared__ float out1s[64];
    int tid=threadIdx.x; int b=blockIdx.x;
    for(int n=tid;n<1024;n+=256){
        float sum=b1[n];
        #pragma unroll
        for(int ks=0;ks<KSPLIT;ks++) sum+=g_part[((size_t)ks*Bn+b)*N1+n];
        y1[n]=sum;
    }
    int o=tid&63, part=tid>>6;
    float acc=0.f;
    for(int chunk=0;chunk<16;chunk++){
        int kbase=chunk*64;
        __syncthreads();
        #pragma unroll
        for(int i=0;i<4;i++){
            int lin=tid+i*256; int row=lin>>4, col4=lin&15;
            float4 f=*(const float4*)(W2 + row*1024 + kbase + col4*4);
            w2s[(col4*4+0)*64+row]=f.x;
            w2s[(col4*4+1)*64+row]=f.y;
            w2s[(col4*4+2)*64+row]=f.z;
            w2s[(col4*4+3)*64+row]=f.w;
        }
        __syncthreads();
        #pragma unroll
        for(int i=0;i<16;i++){
            int k=part*16+i;
            acc += y1[kbase+k]*w2s[k*64+o];
        }
    }
    partial[part*64+o]=acc;
    __syncthreads();
    if(tid<64){
        float v=partial[tid]+partial[64+tid]+partial[128+tid]+partial[192+tid]+b2[tid];
        out1s[tid]=v;
        dout[b*64+tid]=v;
    }
    __syncthreads();
    if(tid<2){
        float s=b3[tid];
        #pragma unroll
        for(int k=0;k<64;k++) s+=out1s[k]*W3[tid*64+k];
        dout[Bn*64 + b*2 + tid]=s;
    }
}

// ================= launch =================
extern "C" void kernel_launch(void* const* d_in, const int* in_sizes, int n_in,
                              void* d_out, int out_size)
{
    const float* x =(const float*)d_in[0];
    const float* Wq=(const float*)d_in[1];  const float* bq=(const float*)d_in[2];
    const float* Wk=(const float*)d_in[3];  const float* bk=(const float*)d_in[4];
    const float* Wv=(const float*)d_in[5];  const float* bv=(const float*)d_in[6];
    const float* Wo=(const float*)d_in[7];  const float* bo=(const float*)d_in[8];
    const float* W1=(const float*)d_in[9];  const float* b1=(const float*)d_in[10];
    const float* W2=(const float*)d_in[11]; const float* b2=(const float*)d_in[12];
    const float* W3=(const float*)d_in[13]; const float* b3=(const float*)d_in[14];
    float* out=(float*)d_out;

    k_qkv <<<(Bn*Sn)/8, 256>>>(x,Wq,bq,Wk,bk,Wv,bv);
    k_attn<<<BHn, 128>>>();
    k_proj<<<Sn, 256>>>(Wo,bo);
    k_fc1 <<<dim3(NBt,KSPLIT), 64>>>(W1);
    k_fc23<<<Bn, 256>>>(b1,W2,b2,W3,b3,out);
}

// round 5
// speedup vs baseline: 1.5079x; 1.0102x over previous
#include <cuda_runtime.h>

#define Bn 128
#define Sn 500
#define Dn 32
#define Hn 8
#define HSn 4
#define BHn (Bn*Hn)        // 1024
#define FCIN (Sn*Dn)       // 16000
#define N1 1024
#define KSPLIT 50
#define KSPAN (FCIN/KSPLIT) // 320
#define BKt 16
#define NT (KSPAN/BKt)      // 20
#define NBt 16              // n-blocks of 64

typedef unsigned long long u64;

// ---------------- scratch (no allocation allowed) ----------------
__device__ float g_q[BHn*Sn*HSn];
__device__ float g_k[BHn*Sn*HSn];
__device__ float g_v[BHn*Sn*HSn];
__device__ float g_av[Bn*Sn*Dn];
__device__ float g_flatT[FCIN*Bn];          // [16000][128]
__device__ float g_part[KSPLIT*Bn*N1];      // split-K partials [ks][m][n]

// ---------------- f32x2 helpers ----------------
__device__ __forceinline__ u64 pack2(float lo, float hi){ u64 r; asm("mov.b64 %0,{%1,%2};" : "=l"(r) : "f"(lo),"f"(hi)); return r; }
__device__ __forceinline__ void unpack2(u64 v, float& lo, float& hi){ asm("mov.b64 {%0,%1},%2;" : "=f"(lo),"=f"(hi) : "l"(v)); }
__device__ __forceinline__ u64 fma2(u64 a,u64 b,u64 c){ u64 d; asm("fma.rn.f32x2 %0,%1,%2,%3;" : "=l"(d) : "l"(a),"l"(b),"l"(c)); return d; }
__device__ __forceinline__ u64 mul2(u64 a,u64 b){ u64 d; asm("mul.rn.f32x2 %0,%1,%2;" : "=l"(d) : "l"(a),"l"(b)); return d; }
__device__ __forceinline__ u64 add2(u64 a,u64 b){ u64 d; asm("add.rn.f32x2 %0,%1,%2;" : "=l"(d) : "l"(a),"l"(b)); return d; }
__device__ __forceinline__ u64 ex2_2(u64 x){
    u64 r;
    asm("{\n\t.reg .f32 a,b;\n\t"
        "mov.b64 {a,b},%1;\n\t"
        "ex2.approx.ftz.f32 a,a;\n\t"
        "ex2.approx.ftz.f32 b,b;\n\t"
        "mov.b64 %0,{a,b};\n\t}" : "=l"(r) : "l"(x));
    return r;
}
__device__ __forceinline__ unsigned smem_u32(const void* p){ return (unsigned)__cvta_generic_to_shared(p); }
__device__ __forceinline__ void cpasync16(unsigned dst, const void* src){
    asm volatile("cp.async.ca.shared.global [%0], [%1], 16;" :: "r"(dst), "l"(src) : "memory");
}
__device__ __forceinline__ void cpcommit(){ asm volatile("cp.async.commit_group;" ::: "memory"); }
__device__ __forceinline__ void cpwait0(){ asm volatile("cp.async.wait_group 0;" ::: "memory"); }

#define QSCALE 0.72134752044448169f   // (1/sqrt(4)) * log2(e), folded into q

// ================= K1: QKV projection (conflict-free padded weights) =================
__global__ __launch_bounds__(256) void k_qkv(const float* __restrict__ x,
    const float* __restrict__ Wq, const float* __restrict__ bq,
    const float* __restrict__ Wk, const float* __restrict__ bk,
    const float* __restrict__ Wv, const float* __restrict__ bv)
{
    __shared__ float ws[3*1056];     // [which][ch][33]
    __shared__ float bs[3*32];
    __shared__ float xs[8*32];
    int tid = threadIdx.x;
    for(int i=tid;i<1024;i+=256){
        int ch=i>>5, k=i&31; int d=ch*33+k;
        ws[d]=Wq[i]; ws[1056+d]=Wk[i]; ws[2112+d]=Wv[i];
    }
    if(tid<32){ bs[tid]=bq[tid]; bs[32+tid]=bk[tid]; bs[64+tid]=bv[tid]; }
    int row0 = blockIdx.x*8;
    xs[tid]=x[row0*32+tid];
    __syncthreads();
    #pragma unroll
    for(int t=0;t<3;t++){
        int o = tid + t*256;
        int row = o/96; int cc = o - row*96;
        int which = cc>>5; int ch = cc&31;
        const float* w  = ws + which*1056 + ch*33;
        const float* xr = xs + row*32;
        float sum = bs[which*32+ch];
        #pragma unroll
        for(int i=0;i<32;i++) sum += xr[i]*w[i];
        int gr = row0+row; int b = gr/Sn; int s = gr - b*Sn;
        int idx = ((b*Hn + (ch>>2))*Sn + s)*HSn + (ch&3);
        if(which==0)      g_q[idx] = sum*QSCALE;
        else if(which==1) g_k[idx] = sum;
        else              g_v[idx] = sum;
    }
}

// ================= K2: attention per (b,h) =================
__global__ __launch_bounds__(128) void k_attn()
{
    __shared__ __align__(16) u64 kk[Sn*HSn];
    __shared__ __align__(16) u64 vv[Sn*HSn];
    int tid=threadIdx.x; int bh=blockIdx.x;
    int base = bh*Sn*HSn;
    for(int i=tid;i<Sn*HSn;i+=128){
        float f=g_k[base+i]; kk[i]=pack2(f,f);
        float g=g_v[base+i]; vv[i]=pack2(g,g);
    }
    __syncthreads();
    if(tid<125){
        int r0=tid, r1=tid+125, r2=tid+250, r3=tid+375;
        const float4* q4=(const float4*)(g_q+base);
        float4 qa=q4[r0], qb=q4[r1], qc=q4[r2], qd=q4[r3];
        u64 qp01[4]={pack2(qa.x,qb.x),pack2(qa.y,qb.y),pack2(qa.z,qb.z),pack2(qa.w,qb.w)};
        u64 qp23[4]={pack2(qc.x,qd.x),pack2(qc.y,qd.y),pack2(qc.z,qd.z),pack2(qc.w,qd.w)};
        u64 acc01[4]={0,0,0,0}, acc23[4]={0,0,0,0};
        u64 l01=0, l23=0;
        #pragma unroll 4
        for(int j=0;j<Sn;j++){
            const ulonglong2* kj=(const ulonglong2*)(kk + j*HSn);
            ulonglong2 K0=kj[0], K1=kj[1];
            u64 d01 = mul2(qp01[0],K0.x); d01=fma2(qp01[1],K0.y,d01);
            d01=fma2(qp01[2],K1.x,d01);   d01=fma2(qp01[3],K1.y,d01);
            u64 d23 = mul2(qp23[0],K0.x); d23=fma2(qp23[1],K0.y,d23);
            d23=fma2(qp23[2],K1.x,d23);   d23=fma2(qp23[3],K1.y,d23);
            u64 p01 = ex2_2(d01);
            u64 p23 = ex2_2(d23);
            l01=add2(l01,p01); l23=add2(l23,p23);
            const ulonglong2* vj=(const ulonglong2*)(vv + j*HSn);
            ulonglong2 V0=vj[0], V1=vj[1];
            acc01[0]=fma2(p01,V0.x,acc01[0]); acc01[1]=fma2(p01,V0.y,acc01[1]);
            acc01[2]=fma2(p01,V1.x,acc01[2]); acc01[3]=fma2(p01,V1.y,acc01[3]);
            acc23[0]=fma2(p23,V0.x,acc23[0]); acc23[1]=fma2(p23,V0.y,acc23[1]);
            acc23[2]=fma2(p23,V1.x,acc23[2]); acc23[3]=fma2(p23,V1.y,acc23[3]);
        }
        int b=bh>>3, h=bh&7;
        float l0,l1,l2,l3; unpack2(l01,l0,l1); unpack2(l23,l2,l3);
        float i0=1.f/l0, i1=1.f/l1, i2=1.f/l2, i3=1.f/l3;
        float lo,hi; float4 o0,o1,o2,o3;
        unpack2(acc01[0],lo,hi); o0.x=lo*i0; o1.x=hi*i1;
        unpack2(acc01[1],lo,hi); o0.y=lo*i0; o1.y=hi*i1;
        unpack2(acc01[2],lo,hi); o0.z=lo*i0; o1.z=hi*i1;
        unpack2(acc01[3],lo,hi); o0.w=lo*i0; o1.w=hi*i1;
        unpack2(acc23[0],lo,hi); o2.x=lo*i2; o3.x=hi*i3;
        unpack2(acc23[1],lo,hi); o2.y=lo*i2; o3.y=hi*i3;
        unpack2(acc23[2],lo,hi); o2.z=lo*i2; o3.z=hi*i3;
        unpack2(acc23[3],lo,hi); o2.w=lo*i2; o3.w=hi*i3;
        float* outb = g_av + b*(Sn*Dn) + h*HSn;
        *(float4*)(outb + r0*Dn) = o0;
        *(float4*)(outb + r1*Dn) = o1;
        *(float4*)(outb + r2*Dn) = o2;
        *(float4*)(outb + r3*Dn) = o3;
    }
}

// ================= K3: Wo projection, writes TRANSPOSED flat =================
__global__ __launch_bounds__(256) void k_proj(const float* __restrict__ Wo,
                                              const float* __restrict__ bo)
{
    __shared__ float avs[128*33];
    __shared__ float wos[1024];
    __shared__ float bos[32];
    int tid=threadIdx.x; int s=blockIdx.x;
    for(int i=tid;i<1024;i+=256) wos[i]=Wo[i];
    if(tid<32) bos[tid]=bo[tid];
    for(int i=tid;i<4096;i+=256){ int bb=i>>5, c=i&31; avs[bb*33+c]=g_av[bb*(Sn*Dn)+s*Dn+c]; }
    __syncthreads();
    #pragma unroll
    for(int t=0;t<16;t++){
        int o=tid+t*256; int bb=o&127, c=o>>7;
        const float* av=avs+bb*33; const float* w=wos+c*32;
        float sum=bos[c];
        #pragma unroll
        for(int i=0;i<32;i++) sum+=av[i]*w[i];
        g_flatT[(s*32+c)*Bn + bb] = sum;
    }
}

// ================= K4: FC1 split-K GEMM v4 =================
// grid (16, 50) = 800 CTAs, 128 thr, 4 warps/CTA, <=128 regs -> 4 CTAs/SM = 16 warps.
// CTA tile 128m x 64n; thread tile 8 m-pairs x 4 n (acc = 32 u64 = 64 regs).
__global__ __launch_bounds__(128,4) void k_fc1(const float* __restrict__ W1)
{
    __shared__ __align__(16) u64 As[2][BKt*64];   // [kk][pair]    8KB each
    __shared__ __align__(16) u64 Bs[2][BKt*64];   // [kk][n] dup   8KB each
    int tid=threadIdx.x;
    int n0=blockIdx.x*64, k0=blockIdx.y*KSPAN;
    int tp=tid>>4, tn=tid&15;           // 8 m-groups, 16 n-groups
    int c0=tn*4;
    u64 acc[32];
    #pragma unroll
    for(int i=0;i<32;i++) acc[i]=0;

    const char* aSrcBase=(const char*)g_flatT + (size_t)k0*512;
    unsigned aDst0 = smem_u32(As[0]) + (unsigned)tid*16;
    unsigned aDst1 = smem_u32(As[1]) + (unsigned)tid*16;
    // B: thread owns half of W1 row n0+(tid>>1): 8 floats at offset (tid&1)*8
    int brow = tid>>1, boff = (tid&1)*8;
    const float* wRow = W1 + (size_t)(n0+brow)*FCIN + k0 + boff;

    {   // prologue tile 0
        #pragma unroll
        for(int j=0;j<4;j++) cpasync16(aDst0 + j*2048, aSrcBase + tid*16 + j*2048);
        cpcommit();
        float4 f0=*(const float4*)(wRow), f1=*(const float4*)(wRow+4);
        u64* B=Bs[0];
        B[(boff+0)*64+brow]=pack2(f0.x,f0.x); B[(boff+1)*64+brow]=pack2(f0.y,f0.y);
        B[(boff+2)*64+brow]=pack2(f0.z,f0.z); B[(boff+3)*64+brow]=pack2(f0.w,f0.w);
        B[(boff+4)*64+brow]=pack2(f1.x,f1.x); B[(boff+5)*64+brow]=pack2(f1.y,f1.y);
        B[(boff+6)*64+brow]=pack2(f1.z,f1.z); B[(boff+7)*64+brow]=pack2(f1.w,f1.w);
    }

    for(int t=0;t<NT;t++){
        cpwait0();
        __syncthreads();
        if(t+1<NT){
            int nb=(t+1)&1;
            const char* a = aSrcBase + (size_t)(t+1)*8192;
            unsigned d = nb? aDst1 : aDst0;
            #pragma unroll
            for(int j=0;j<4;j++) cpasync16(d + j*2048, a + tid*16 + j*2048);
            cpcommit();
            const float* w = wRow + (t+1)*BKt;
            float4 f0=*(const float4*)(w), f1=*(const float4*)(w+4);
            u64* B=Bs[nb];
            B[(boff+0)*64+brow]=pack2(f0.x,f0.x); B[(boff+1)*64+brow]=pack2(f0.y,f0.y);
            B[(boff+2)*64+brow]=pack2(f0.z,f0.z); B[(boff+3)*64+brow]=pack2(f0.w,f0.w);
            B[(boff+4)*64+brow]=pack2(f1.x,f1.x); B[(boff+5)*64+brow]=pack2(f1.y,f1.y);
            B[(boff+6)*64+brow]=pack2(f1.z,f1.z); B[(boff+7)*64+brow]=pack2(f1.w,f1.w);
        }
        const u64* A=As[t&1]; const u64* B=Bs[t&1];
        #pragma unroll
        for(int kkk=0;kkk<BKt;kkk++){
            const ulonglong2* ap=(const ulonglong2*)(A + kkk*64 + tp*2);
            ulonglong2 A0=ap[0],A1=ap[8],A2=ap[16],A3=ap[24];
            const ulonglong2* bp=(const ulonglong2*)(B + kkk*64 + c0);
            ulonglong2 B0=bp[0],B1=bp[1];
            u64 a_[8]={A0.x,A0.y,A1.x,A1.y,A2.x,A2.y,A3.x,A3.y};
            u64 b_[4]={B0.x,B0.y,B1.x,B1.y};
            #pragma unroll
            for(int i=0;i<8;i++)
                #pragma unroll
                for(int j=0;j<4;j++)
                    acc[i*4+j]=fma2(a_[i],b_[j],acc[i*4+j]);
        }
    }

    // staged, coalesced partial writes: g_part[ks][m][n]
    float* smf = (float*)As;        // 16KB = 64m x 64n floats
    int ks = blockIdx.y;
    #pragma unroll
    for(int c=0;c<2;c++){
        __syncthreads();
        #pragma unroll
        for(int q=0;q<2;q++){
            #pragma unroll
            for(int e=0;e<2;e++){
                int ii = c*4 + q*2 + e;          // acc i index
                int mi = 4*tp + 32*q + 2*e;      // local m row in chunk
                #pragma unroll
                for(int jj=0;jj<4;jj++){
                    float lo,hi; unpack2(acc[ii*4+jj],lo,hi);
                    int nl = c0+jj;
                    smf[mi*64+nl]=lo;
                    smf[(mi+1)*64+nl]=hi;
                }
            }
        }
        __syncthreads();
        #pragma unroll
        for(int i=0;i<8;i++){
            int fid = i*128 + tid;               // float4 id 0..1023
            int row = fid>>4, col4 = fid&15;
            float4 v = *(const float4*)(smf + row*64 + col4*4);
            *(float4*)(g_part + ((size_t)(ks*Bn) + c*64 + row)*N1 + n0 + col4*4) = v;
        }
    }
}

// ================= K5: split-K reduce + FC2 + FC3 =================
__global__ __launch_bounds__(256) void k_fc23(const float* __restrict__ b1,
    const float* __restrict__ W2, const float* __restrict__ b2,
    const float* __restrict__ W3, const float* __restrict__ b3,
    float* __restrict__ dout)
{
    __shared__ float y1[1024];
    __shared__ float w2s[64*64];
    __shared__ float partial[4*64];
    __shared__ float out1s[64];
    int tid=threadIdx.x; int b=blockIdx.x;
    for(int n=tid;n<1024;n+=256){
        float sum=b1[n];
        #pragma unroll
        for(int ks=0;ks<KSPLIT;ks++) sum+=g_part[((size_t)ks*Bn+b)*N1+n];
        y1[n]=sum;
    }
    int o=tid&63, part=tid>>6;
    float acc=0.f;
    for(int chunk=0;chunk<16;chunk++){
        int kbase=chunk*64;
        __syncthreads();
        #pragma unroll
        for(int i=0;i<4;i++){
            int lin=tid+i*256; int row=lin>>4, col4=lin&15;
            float4 f=*(const float4*)(W2 + row*1024 + kbase + col4*4);
            w2s[(col4*4+0)*64+row]=f.x;
            w2s[(col4*4+1)*64+row]=f.y;
            w2s[(col4*4+2)*64+row]=f.z;
            w2s[(col4*4+3)*64+row]=f.w;
        }
        __syncthreads();
        #pragma unroll
        for(int i=0;i<16;i++){
            int k=part*16+i;
            acc += y1[kbase+k]*w2s[k*64+o];
        }
    }
    partial[part*64+o]=acc;
    __syncthreads();
    if(tid<64){
        float v=partial[tid]+partial[64+tid]+partial[128+tid]+partial[192+tid]+b2[tid];
        out1s[tid]=v;
        dout[b*64+tid]=v;
    }
    __syncthreads();
    if(tid<2){
        float s=b3[tid];
        #pragma unroll
        for(int k=0;k<64;k++) s+=out1s[k]*W3[tid*64+k];
        dout[Bn*64 + b*2 + tid]=s;
    }
}

// ================= launch =================
extern "C" void kernel_launch(void* const* d_in, const int* in_sizes, int n_in,
                              void* d_out, int out_size)
{
    const float* x =(const float*)d_in[0];
    const float* Wq=(const float*)d_in[1];  const float* bq=(const float*)d_in[2];
    const float* Wk=(const float*)d_in[3];  const float* bk=(const float*)d_in[4];
    const float* Wv=(const float*)d_in[5];  const float* bv=(const float*)d_in[6];
    const float* Wo=(const float*)d_in[7];  const float* bo=(const float*)d_in[8];
    const float* W1=(const float*)d_in[9];  const float* b1=(const float*)d_in[10];
    const float* W2=(const float*)d_in[11]; const float* b2=(const float*)d_in[12];
    const float* W3=(const float*)d_in[13]; const float* b3=(const float*)d_in[14];
    float* out=(float*)d_out;

    k_qkv <<<(Bn*Sn)/8, 256>>>(x,Wq,bq,Wk,bk,Wv,bv);
    k_attn<<<BHn, 128>>>();
    k_proj<<<Sn, 256>>>(Wo,bo);
    k_fc1 <<<dim3(NBt,KSPLIT), 128>>>(W1);
    k_fc23<<<Bn, 256>>>(b1,W2,b2,W3,b3,out);
}

// round 7
// speedup vs baseline: 1.6789x; 1.1134x over previous
#include <cuda_runtime.h>
#include <cuda_bf16.h>

#define Bn 128
#define Sn 500
#define Dn 32
#define Hn 8
#define HSn 4
#define BHn (Bn*Hn)        // 1024
#define FCIN (Sn*Dn)       // 16000
#define N1 1024
#define KSPLIT 25
#define KSPAN (FCIN/KSPLIT) // 640
#define KCH 32
#define NCHUNK (KSPAN/KCH)  // 20
#define GBUF 30720          // bytes per smem buffer (Ah 5120 | Al 5120 | Bh 10240 | Bl 10240)
#define GEMM_SMEM (2*GBUF)

typedef unsigned long long u64;

// ---------------- scratch (no allocation allowed) ----------------
__device__ float g_q[BHn*Sn*HSn];
__device__ float g_k[BHn*Sn*HSn];
__device__ float g_v[BHn*Sn*HSn];
__device__ float g_av[Bn*Sn*Dn];
__device__ __align__(128) __nv_bfloat16 g_w1h[(size_t)N1*FCIN];
__device__ __align__(128) __nv_bfloat16 g_w1l[(size_t)N1*FCIN];
__device__ __align__(128) __nv_bfloat16 g_fh[(size_t)Bn*FCIN];
__device__ __align__(128) __nv_bfloat16 g_fl[(size_t)Bn*FCIN];
__device__ float g_part[(size_t)KSPLIT*N1*Bn];   // [ks][n(1024)][b(128)]
__device__ float g_y1T[N1*Bn];                   // [n][b]

// ---------------- f32x2 + misc helpers ----------------
__device__ __forceinline__ u64 pack2(float lo, float hi){ u64 r; asm("mov.b64 %0,{%1,%2};" : "=l"(r) : "f"(lo),"f"(hi)); return r; }
__device__ __forceinline__ void unpack2(u64 v, float& lo, float& hi){ asm("mov.b64 {%0,%1},%2;" : "=f"(lo),"=f"(hi) : "l"(v)); }
__device__ __forceinline__ u64 fma2(u64 a,u64 b,u64 c){ u64 d; asm("fma.rn.f32x2 %0,%1,%2,%3;" : "=l"(d) : "l"(a),"l"(b),"l"(c)); return d; }
__device__ __forceinline__ u64 mul2(u64 a,u64 b){ u64 d; asm("mul.rn.f32x2 %0,%1,%2;" : "=l"(d) : "l"(a),"l"(b)); return d; }
__device__ __forceinline__ u64 add2(u64 a,u64 b){ u64 d; asm("add.rn.f32x2 %0,%1,%2;" : "=l"(d) : "l"(a),"l"(b)); return d; }
__device__ __forceinline__ u64 ex2_2(u64 x){
    u64 r;
    asm("{\n\t.reg .f32 a,b;\n\t"
        "mov.b64 {a,b},%1;\n\t"
        "ex2.approx.ftz.f32 a,a;\n\t"
        "ex2.approx.ftz.f32 b,b;\n\t"
        "mov.b64 %0,{a,b};\n\t}" : "=l"(r) : "l"(x));
    return r;
}
__device__ __forceinline__ unsigned smem_u32(const void* p){ return (unsigned)__cvta_generic_to_shared(p); }
__device__ __forceinline__ void cpasync16(unsigned dst, const void* src){
    asm volatile("cp.async.ca.shared.global [%0], [%1], 16;" :: "r"(dst), "l"(src) : "memory");
}
__device__ __forceinline__ void cpcommit(){ asm volatile("cp.async.commit_group;" ::: "memory"); }
__device__ __forceinline__ void cpwait0(){ asm volatile("cp.async.wait_group 0;" ::: "memory"); }

__device__ __forceinline__ void ldsm4(unsigned* r, unsigned addr){
    asm volatile("ldmatrix.sync.aligned.m8n8.x4.shared.b16 {%0,%1,%2,%3},[%4];"
        : "=r"(r[0]),"=r"(r[1]),"=r"(r[2]),"=r"(r[3]) : "r"(addr));
}
__device__ __forceinline__ void mma16816(float* d, const unsigned* a, const unsigned* b){
    asm volatile("mma.sync.aligned.m16n8k16.row.col.f32.bf16.bf16.f32 "
        "{%0,%1,%2,%3},{%4,%5,%6,%7},{%8,%9},{%0,%1,%2,%3};"
        : "+f"(d[0]),"+f"(d[1]),"+f"(d[2]),"+f"(d[3])
        : "r"(a[0]),"r"(a[1]),"r"(a[2]),"r"(a[3]),"r"(b[0]),"r"(b[1]));
}

#define QSCALE 0.72134752044448169f   // (1/sqrt(4)) * log2(e), folded into q

// ================= K0: W1 -> bf16 hi/lo =================
__global__ __launch_bounds__(256) void k_cvt(const float* __restrict__ W1)
{
    size_t i0 = ((size_t)blockIdx.x*256 + threadIdx.x)*8;
    float4 a=*(const float4*)(W1+i0), b=*(const float4*)(W1+i0+4);
    float v[8]={a.x,a.y,a.z,a.w,b.x,b.y,b.z,b.w};
    union { __nv_bfloat16 s[8]; uint4 u; } H, L;
    #pragma unroll
    for(int j=0;j<8;j++){
        __nv_bfloat16 h=__float2bfloat16(v[j]);
        H.s[j]=h;
        L.s[j]=__float2bfloat16(v[j]-__bfloat162float(h));
    }
    *(uint4*)(g_w1h+i0)=H.u;
    *(uint4*)(g_w1l+i0)=L.u;
}

// ================= K1: QKV projection (conflict-free padded weights) =================
__global__ __launch_bounds__(256) void k_qkv(const float* __restrict__ x,
    const float* __restrict__ Wq, const float* __restrict__ bq,
    const float* __restrict__ Wk, const float* __restrict__ bk,
    const float* __restrict__ Wv, const float* __restrict__ bv)
{
    __shared__ float ws[3*1056];
    __shared__ float bs[3*32];
    __shared__ float xs[8*32];
    int tid = threadIdx.x;
    for(int i=tid;i<1024;i+=256){
        int ch=i>>5, k=i&31; int d=ch*33+k;
        ws[d]=Wq[i]; ws[1056+d]=Wk[i]; ws[2112+d]=Wv[i];
    }
    if(tid<32){ bs[tid]=bq[tid]; bs[32+tid]=bk[tid]; bs[64+tid]=bv[tid]; }
    int row0 = blockIdx.x*8;
    xs[tid]=x[row0*32+tid];
    __syncthreads();
    #pragma unroll
    for(int t=0;t<3;t++){
        int o = tid + t*256;
        int row = o/96; int cc = o - row*96;
        int which = cc>>5; int ch = cc&31;
        const float* w  = ws + which*1056 + ch*33;
        const float* xr = xs + row*32;
        float sum = bs[which*32+ch];
        #pragma unroll
        for(int i=0;i<32;i++) sum += xr[i]*w[i];
        int gr = row0+row; int b = gr/Sn; int s = gr - b*Sn;
        int idx = ((b*Hn + (ch>>2))*Sn + s)*HSn + (ch&3);
        if(which==0)      g_q[idx] = sum*QSCALE;
        else if(which==1) g_k[idx] = sum;
        else              g_v[idx] = sum;
    }
}

// ================= K2: attention per (b,h) =================
__global__ __launch_bounds__(128) void k_attn()
{
    __shared__ __align__(16) u64 kk[Sn*HSn];
    __shared__ __align__(16) u64 vv[Sn*HSn];
    int tid=threadIdx.x; int bh=blockIdx.x;
    int base = bh*Sn*HSn;
    for(int i=tid;i<Sn*HSn;i+=128){
        float f=g_k[base+i]; kk[i]=pack2(f,f);
        float g=g_v[base+i]; vv[i]=pack2(g,g);
    }
    __syncthreads();
    if(tid<125){
        int r0=tid, r1=tid+125, r2=tid+250, r3=tid+375;
        const float4* q4=(const float4*)(g_q+base);
        float4 qa=q4[r0], qb=q4[r1], qc=q4[r2], qd=q4[r3];
        u64 qp01[4]={pack2(qa.x,qb.x),pack2(qa.y,qb.y),pack2(qa.z,qb.z),pack2(qa.w,qb.w)};
        u64 qp23[4]={pack2(qc.x,qd.x),pack2(qc.y,qd.y),pack2(qc.z,qd.z),pack2(qc.w,qd.w)};
        u64 acc01[4]={0,0,0,0}, acc23[4]={0,0,0,0};
        u64 l01=0, l23=0;
        #pragma unroll 4
        for(int j=0;j<Sn;j++){
            const ulonglong2* kj=(const ulonglong2*)(kk + j*HSn);
            ulonglong2 K0=kj[0], K1=kj[1];
            u64 d01 = mul2(qp01[0],K0.x); d01=fma2(qp01[1],K0.y,d01);
            d01=fma2(qp01[2],K1.x,d01);   d01=fma2(qp01[3],K1.y,d01);
            u64 d23 = mul2(qp23[0],K0.x); d23=fma2(qp23[1],K0.y,d23);
            d23=fma2(qp23[2],K1.x,d23);   d23=fma2(qp23[3],K1.y,d23);
            u64 p01 = ex2_2(d01);
            u64 p23 = ex2_2(d23);
            l01=add2(l01,p01); l23=add2(l23,p23);
            const ulonglong2* vj=(const ulonglong2*)(vv + j*HSn);
            ulonglong2 V0=vj[0], V1=vj[1];
            acc01[0]=fma2(p01,V0.x,acc01[0]); acc01[1]=fma2(p01,V0.y,acc01[1]);
            acc01[2]=fma2(p01,V1.x,acc01[2]); acc01[3]=fma2(p01,V1.y,acc01[3]);
            acc23[0]=fma2(p23,V0.x,acc23[0]); acc23[1]=fma2(p23,V0.y,acc23[1]);
            acc23[2]=fma2(p23,V1.x,acc23[2]); acc23[3]=fma2(p23,V1.y,acc23[3]);
        }
        int b=bh>>3, h=bh&7;
        float l0,l1,l2,l3; unpack2(l01,l0,l1); unpack2(l23,l2,l3);
        float i0=1.f/l0, i1=1.f/l1, i2=1.f/l2, i3=1.f/l3;
        float lo,hi; float4 o0,o1,o2,o3;
        unpack2(acc01[0],lo,hi); o0.x=lo*i0; o1.x=hi*i1;
        unpack2(acc01[1],lo,hi); o0.y=lo*i0; o1.y=hi*i1;
        unpack2(acc01[2],lo,hi); o0.z=lo*i0; o1.z=hi*i1;
        unpack2(acc01[3],lo,hi); o0.w=lo*i0; o1.w=hi*i1;
        unpack2(acc23[0],lo,hi); o2.x=lo*i2; o3.x=hi*i3;
        unpack2(acc23[1],lo,hi); o2.y=lo*i2; o3.y=hi*i3;
        unpack2(acc23[2],lo,hi); o2.z=lo*i2; o3.z=hi*i3;
        unpack2(acc23[3],lo,hi); o2.w=lo*i2; o3.w=hi*i3;
        float* outb = g_av + b*(Sn*Dn) + h*HSn;
        *(float4*)(outb + r0*Dn) = o0;
        *(float4*)(outb + r1*Dn) = o1;
        *(float4*)(outb + r2*Dn) = o2;
        *(float4*)(outb + r3*Dn) = o3;
    }
}

// ================= K3: Wo projection -> flat bf16 hi/lo [b][k] =================
__global__ __launch_bounds__(256) void k_proj(const float* __restrict__ Wo,
                                              const float* __restrict__ bo)
{
    __shared__ float avs[128*33];
    __shared__ float wosT[1024];   // [k][ch]
    __shared__ float bos[32];
    int tid=threadIdx.x; int s=blockIdx.x;
    for(int i=tid;i<1024;i+=256){ int k=i>>5, ch=i&31; wosT[i]=Wo[ch*32+k]; }
    if(tid<32) bos[tid]=bo[tid];
    for(int i=tid;i<4096;i+=256){ int bb=i>>5, c=i&31; avs[bb*33+c]=g_av[bb*(Sn*Dn)+s*Dn+c]; }
    __syncthreads();
    #pragma unroll
    for(int t=0;t<16;t++){
        int o=tid+t*256; int c=o&31, bb=o>>5;
        const float* av=avs+bb*33;
        float sum=bos[c];
        #pragma unroll
        for(int i=0;i<32;i++) sum+=av[i]*wosT[i*32+c];
        __nv_bfloat16 h=__float2bfloat16(sum);
        __nv_bfloat16 l=__float2bfloat16(sum-__bfloat162float(h));
        size_t k=(size_t)bb*FCIN + s*32 + c;
        g_fh[k]=h; g_fl[k]=l;
    }
}

// ================= K4: FC1 via mma.sync bf16 (hi/lo split, split-K) =================
// grid (16 m-blocks, 25 k-splits), 128 thr (4 warps). CTA tile: 64 W1-rows x 128 batch.
// Warp w covers n = w*32..w*32+31 (batch), all 64 m. 16 m16n8 tiles/warp, 3 MMAs each.
// smem buffer (x2): Ah[64x40bf16] Al[...] Bh[128x40] Bl[...], 80B row pitch (LDSM conflict-free).
__global__ __launch_bounds__(128) void k_gemm()
{
    extern __shared__ __align__(16) char dsm[];
    int tid=threadIdx.x, wid=tid>>5, lane=tid&31;
    int m0 = blockIdx.x*64;
    int ks = blockIdx.y;
    int kbase = ks*KSPAN;
    unsigned smb = smem_u32(dsm);

    float acc[4][4][4];
    #pragma unroll
    for(int i=0;i<4;i++)
        #pragma unroll
        for(int j=0;j<4;j++)
            #pragma unroll
            for(int q=0;q<4;q++) acc[i][j][q]=0.f;

    const char* w1h=(const char*)g_w1h; const char* w1l=(const char*)g_w1l;
    const char* fh =(const char*)g_fh;  const char* fl =(const char*)g_fl;

    // per-thread cp.async id precompute
    int aR = tid>>1, aC2 = (tid&1)*2;          // A: 2 ids/thread: rows tid>>1, cols aC2,aC2+1
    // B: 4 ids/thread: id=tid*4+i -> row=id>>2=tid, col=i
    #define LOAD_CHUNK(t) { \
        unsigned dst = smb + ((t)&1)*GBUF; \
        int kx = kbase + (t)*KCH; \
        size_t soA = ((size_t)(m0+aR)*FCIN + kx)*2; \
        cpasync16(dst + aR*80 + aC2*16,        w1h + soA + aC2*16); \
        cpasync16(dst + aR*80 + (aC2+1)*16,    w1h + soA + (aC2+1)*16); \
        cpasync16(dst + 5120 + aR*80 + aC2*16,     w1l + soA + aC2*16); \
        cpasync16(dst + 5120 + aR*80 + (aC2+1)*16, w1l + soA + (aC2+1)*16); \
        size_t soB = ((size_t)tid*FCIN + kx)*2; \
        _Pragma("unroll") \
        for(int c=0;c<4;c++){ \
            cpasync16(dst + 10240 + tid*80 + c*16, fh + soB + c*16); \
            cpasync16(dst + 20480 + tid*80 + c*16, fl + soB + c*16); \
        } \
        cpcommit(); }

    LOAD_CHUNK(0);
    for(int t=0;t<NCHUNK;t++){
        cpwait0();
        __syncthreads();
        if(t+1<NCHUNK) LOAD_CHUNK(t+1);
        unsigned buf = smb + (t&1)*GBUF;
        #pragma unroll
        for(int kstep=0;kstep<2;kstep++){
            unsigned aAddr = buf + kstep*32 + (lane&15)*80 + (lane>>4)*16;
            unsigned ah[4][4], al[4][4];
            #pragma unroll
            for(int mt=0;mt<4;mt++){
                ldsm4(ah[mt], aAddr + mt*16*80);
                ldsm4(al[mt], aAddr + 5120 + mt*16*80);
            }
            unsigned bAddr = buf + 10240 + kstep*32
                           + (wid*32 + (lane>>4)*8 + (lane&7))*80 + ((lane>>3)&1)*16;
            unsigned bh[2][4], bl[2][4];
            #pragma unroll
            for(int g=0;g<2;g++){
                ldsm4(bh[g], bAddr + g*16*80);
                ldsm4(bl[g], bAddr + 10240 + g*16*80);
            }
            #pragma unroll
            for(int mt=0;mt<4;mt++)
                #pragma unroll
                for(int nt=0;nt<4;nt++){
                    const unsigned* bhf=&bh[nt>>1][(nt&1)*2];
                    const unsigned* blf=&bl[nt>>1][(nt&1)*2];
                    mma16816(acc[mt][nt], ah[mt], bhf);
                    mma16816(acc[mt][nt], ah[mt], blf);
                    mma16816(acc[mt][nt], al[mt], bhf);
                }
        }
    }

    // epilogue: direct stores to g_part[ks][m][b]
    #pragma unroll
    for(int mt=0;mt<4;mt++)
        #pragma unroll
        for(int nt=0;nt<4;nt++){
            int row = m0 + mt*16 + (lane>>2);
            int col = wid*32 + nt*8 + (lane&3)*2;
            float2 v0; v0.x=acc[mt][nt][0]; v0.y=acc[mt][nt][1];
            float2 v1; v1.x=acc[mt][nt][2]; v1.y=acc[mt][nt][3];
            *(float2*)(g_part + ((size_t)ks*N1 + row)*Bn + col) = v0;
            *(float2*)(g_part + ((size_t)ks*N1 + row + 8)*Bn + col) = v1;
        }
}

// ================= K5: split-K reduce + b1 -> y1T[n][b] =================
__global__ __launch_bounds__(256) void k_red(const float* __restrict__ b1)
{
    int n = blockIdx.x*2 + (threadIdx.x>>7);
    int b = threadIdx.x&127;
    float s = b1[n];
    #pragma unroll
    for(int ks=0;ks<KSPLIT;ks++) s += g_part[((size_t)ks*N1+n)*Bn + b];
    g_y1T[n*Bn+b] = s;
}

// ================= K6: FC2 + FC3 =================
__global__ __launch_bounds__(256) void k_fc23(
    const float* __restrict__ W2, const float* __restrict__ b2,
    const float* __restrict__ W3, const float* __restrict__ b3,
    float* __restrict__ dout)
{
    __shared__ float y1[1024];
    __shared__ float w2s[64*64];
    __shared__ float partial[4*64];
    __shared__ float out1s[64];
    int tid=threadIdx.x; int b=blockIdx.x;
    for(int n=tid;n<1024;n+=256) y1[n]=g_y1T[n*Bn+b];
    int o=tid&63, part=tid>>6;
    float acc=0.f;
    for(int chunk=0;chunk<16;chunk++){
        int kbase=chunk*64;
        __syncthreads();
        #pragma unroll
        for(int i=0;i<4;i++){
            int lin=tid+i*256; int row=lin>>4, col4=lin&15;
            float4 f=*(const float4*)(W2 + row*1024 + kbase + col4*4);
            w2s[(col4*4+0)*64+row]=f.x;
            w2s[(col4*4+1)*64+row]=f.y;
            w2s[(col4*4+2)*64+row]=f.z;
            w2s[(col4*4+3)*64+row]=f.w;
        }
        __syncthreads();
        #pragma unroll
        for(int i=0;i<16;i++){
            int k=part*16+i;
            acc += y1[kbase+k]*w2s[k*64+o];
        }
    }
    partial[part*64+o]=acc;
    __syncthreads();
    if(tid<64){
        float v=partial[tid]+partial[64+tid]+partial[128+tid]+partial[192+tid]+b2[tid];
        out1s[tid]=v;
        dout[b*64+tid]=v;
    }
    __syncthreads();
    if(tid<2){
        float s=b3[tid];
        #pragma unroll
        for(int k=0;k<64;k++) s+=out1s[k]*W3[tid*64+k];
        dout[Bn*64 + b*2 + tid]=s;
    }
}

// ================= launch =================
extern "C" void kernel_launch(void* const* d_in, const int* in_sizes, int n_in,
                              void* d_out, int out_size)
{
    const float* x =(const float*)d_in[0];
    const float* Wq=(const float*)d_in[1];  const float* bq=(const float*)d_in[2];
    const float* Wk=(const float*)d_in[3];  const float* bk=(const float*)d_in[4];
    const float* Wv=(const float*)d_in[5];  const float* bv=(const float*)d_in[6];
    const float* Wo=(const float*)d_in[7];  const float* bo=(const float*)d_in[8];
    const float* W1=(const float*)d_in[9];  const float* b1=(const float*)d_in[10];
    const float* W2=(const float*)d_in[11]; const float* b2=(const float*)d_in[12];
    const float* W3=(const float*)d_in[13]; const float* b3=(const float*)d_in[14];
    float* out=(float*)d_out;

    static int smemSet = 0;
    if(!smemSet){
        cudaFuncSetAttribute(k_gemm, cudaFuncAttributeMaxDynamicSharedMemorySize, GEMM_SMEM);
        smemSet = 1;
    }

    k_cvt <<<8000, 256>>>(W1);
    k_qkv <<<(Bn*Sn)/8, 256>>>(x,Wq,bq,Wk,bk,Wv,bv);
    k_attn<<<BHn, 128>>>();
    k_proj<<<Sn, 256>>>(Wo,bo);
    k_gemm<<<dim3(16,KSPLIT), 128, GEMM_SMEM>>>();
    k_red <<<N1/2, 256>>>(b1);
    k_fc23<<<Bn, 256>>>(W2,b2,W3,b3,out);
}